// round 6
// baseline (speedup 1.0000x reference)
#include <cuda_runtime.h>

#define S_LEN 1024
#define NP 513
#define PSTR 516
#define OUT_ELEMS 4194304
#define NROWS 65536

__device__ float g_P[(size_t)NROWS * PSTR];   // P[row,p] = q[row]·Wk[p]
__device__ float g_C[(size_t)NROWS * PSTR];   // unnormalized shifted weights E
__device__ float g_SInv[NROWS];               // 1/sumexp per row

// ---------------------------------------------------------------------------
// Kernel A: P = Q @ Wk^T, 128x128 tiles, 8x8 accum, full-K resident
// ---------------------------------------------------------------------------
__global__ void __launch_bounds__(256) kernA(const float* __restrict__ q,
                                             const float* __restrict__ Wk) {
    const int r0 = blockIdx.x * 128;
    const int p0 = blockIdx.y * 128;
    const int i0 = r0 & (S_LEN - 1);
    if (p0 + 127 < 385 - i0) return;   // tile entirely below min needed p
    extern __shared__ float dsmA[];
    float (*sQT)[132] = (float(*)[132])(dsmA);          // [d][r]
    float (*sWT)[132] = (float(*)[132])(dsmA + 8448);   // [d][p-p0]
    const int tid = threadIdx.x;
    #pragma unroll
    for (int l = 0; l < 8; ++l) {
        int e = tid + l * 256;
        int r = e & 127, c4 = (e >> 7) << 2;
        float4 vv = *(const float4*)(q + (size_t)(r0 + r) * 64 + c4);
        sQT[c4+0][r]=vv.x; sQT[c4+1][r]=vv.y; sQT[c4+2][r]=vv.z; sQT[c4+3][r]=vv.w;
    }
    #pragma unroll
    for (int l = 0; l < 8; ++l) {
        int e = tid + l * 256;
        int r = e & 127, c4 = (e >> 7) << 2;
        int p = p0 + r;
        float4 vv = make_float4(0.f,0.f,0.f,0.f);
        if (p < NP) vv = *(const float4*)(Wk + (size_t)p * 64 + c4);
        sWT[c4+0][r]=vv.x; sWT[c4+1][r]=vv.y; sWT[c4+2][r]=vv.z; sWT[c4+3][r]=vv.w;
    }
    __syncthreads();
    const int tx = tid & 15, ty = tid >> 4;
    float acc[8][8] = {};
    #pragma unroll 8
    for (int d = 0; d < 64; ++d) {
        float a[8], b[8];
        *(float4*)&a[0] = *(const float4*)&sQT[d][4*ty];
        *(float4*)&a[4] = *(const float4*)&sQT[d][4*ty + 64];
        *(float4*)&b[0] = *(const float4*)&sWT[d][4*tx];
        *(float4*)&b[4] = *(const float4*)&sWT[d][4*tx + 64];
        #pragma unroll
        for (int ri = 0; ri < 8; ++ri)
            #pragma unroll
            for (int ci = 0; ci < 8; ++ci)
                acc[ri][ci] += a[ri] * b[ci];
    }
    #pragma unroll
    for (int rs = 0; rs < 8; ++rs) {
        const int r = r0 + ((rs < 4) ? 4*ty + rs : 64 + 4*ty + rs - 4);
        const size_t row = (size_t)r * PSTR;
        const int c0 = p0 + 4*tx;
        if (c0 <= 512)
            *(float4*)(g_P + row + c0) = make_float4(acc[rs][0],acc[rs][1],acc[rs][2],acc[rs][3]);
        const int c1 = p0 + 64 + 4*tx;
        if (c1 <= 512)
            *(float4*)(g_P + row + c1) = make_float4(acc[rs][4],acc[rs][5],acc[rs][6],acc[rs][7]);
    }
}

// ---------------------------------------------------------------------------
// Fused B+C: no-max softmax; conflict-free transposed smem stores.
// ---------------------------------------------------------------------------
__global__ void __launch_bounds__(256) kernBC(const float* __restrict__ q,
                                              const float* __restrict__ kmat,
                                              const float* __restrict__ v,
                                              float* __restrict__ wbuf,
                                              float* __restrict__ outp) {
    extern __shared__ float dsm[];
    float (*sQT)[68] = (float(*)[68])(dsm);
    float (*sKT)[68] = (float(*)[68])(dsm + 4352);
    float (*sV)[68]  = (float(*)[68])(dsm + 8704);
    float (*sET)[68] = (float(*)[68])(dsm + 13056);
    float *sS   = dsm + 17408;
    float *sCs  = dsm + 17472;
    float *sInv = dsm + 17536;

    const int bh = blockIdx.y;
    const int ib = 15 - (int)blockIdx.x;     // heavy blocks first
    const int i0 = ib * 64;
    const int rowbase = bh * S_LEN + i0;
    const int tid = threadIdx.x;
    const int tx = tid & 15, ty = tid >> 4;
    const int rl = ty << 2, cl = tx << 2;

    // Q transposed load: r across lanes -> conflict-free scalar STS
    #pragma unroll
    for (int l = 0; l < 4; ++l) {
        int e = tid + l * 256;
        int r = e & 63, c4 = (e >> 6) << 2;
        float4 vv = *(const float4*)(q + (size_t)(rowbase + r) * 64 + c4);
        sQT[c4+0][r]=vv.x; sQT[c4+1][r]=vv.y; sQT[c4+2][r]=vv.z; sQT[c4+3][r]=vv.w;
    }
    if (tid < 64) { sS[tid] = 0.f; sCs[tid] = 0.f; }

    float accO[4][4] = {};

    for (int jb = 0; jb <= ib; ++jb) {
        const int j0 = jb * 64;
        __syncthreads();
        // K transposed load: r across lanes -> conflict-free scalar STS
        #pragma unroll
        for (int l = 0; l < 4; ++l) {
            int e = tid + l * 256;
            int r = e & 63, c4 = (e >> 6) << 2;
            float4 vv = *(const float4*)(kmat + (size_t)(bh*S_LEN + j0 + r)*64 + c4);
            sKT[c4+0][r]=vv.x; sKT[c4+1][r]=vv.y; sKT[c4+2][r]=vv.z; sKT[c4+3][r]=vv.w;
        }
        #pragma unroll
        for (int l = 0; l < 4; ++l) {
            int e = tid + l * 256;
            int r = e >> 4, c4 = (e & 15) << 2;
            *(float4*)&sV[r][c4] = *(const float4*)(v + (size_t)(bh*S_LEN + j0 + r)*64 + c4);
        }
        __syncthreads();

        float accQ[4][4] = {};
        #pragma unroll 16
        for (int d = 0; d < 64; ++d) {
            float4 a4 = *(const float4*)&sQT[d][rl];
            float4 b4 = *(const float4*)&sKT[d][cl];
            const float a[4] = {a4.x, a4.y, a4.z, a4.w};
            const float b[4] = {b4.x, b4.y, b4.z, b4.w};
            #pragma unroll
            for (int ri = 0; ri < 4; ++ri)
                #pragma unroll
                for (int ci = 0; ci < 4; ++ci)
                    accQ[ri][ci] += a[ri] * b[ci];
        }

        // bias + mask + exp + rowsum + scatter
        #pragma unroll
        for (int ri = 0; ri < 4; ++ri) {
            const int r = rl + ri;
            const int i = i0 + r;
            const size_t prow = (size_t)(rowbase + r) * PSTR;
            #pragma unroll
            for (int ci = 0; ci < 4; ++ci) {
                const int j = j0 + cl + ci;
                int p = j - i + 512; if (p < 0) p = 0;
                float l = accQ[ri][ci] + g_P[prow + p];
                if (j > i) l = -1e30f;            // exp -> 0 exactly
                accQ[ri][ci] = __expf(l);
            }
            float se = accQ[ri][0] + accQ[ri][1] + accQ[ri][2] + accQ[ri][3];
            #pragma unroll
            for (int off = 8; off >= 1; off >>= 1)
                se += __shfl_xor_sync(0xffffffffu, se, off);
            if (tx == 0) sS[r] += se;
            // scatter E into g_C (m = i - j)
            #pragma unroll
            for (int ci = 0; ci < 4; ++ci) {
                const int mm = i - (j0 + cl + ci);
                if (mm >= 0) {
                    if (mm < 512) g_C[prow + mm] = accQ[ri][ci];
                    else          atomicAdd(&sCs[r], accQ[ri][ci]);
                }
            }
        }

        // E -> wbuf (raw) + transposed smem via float4-along-r stores
        #pragma unroll
        for (int ri = 0; ri < 4; ++ri)
            *(float4*)(wbuf + (size_t)(rowbase + rl + ri) * S_LEN + j0 + cl)
                = make_float4(accQ[ri][0], accQ[ri][1], accQ[ri][2], accQ[ri][3]);
        #pragma unroll
        for (int ci = 0; ci < 4; ++ci)
            *(float4*)&sET[cl + ci][rl]
                = make_float4(accQ[0][ci], accQ[1][ci], accQ[2][ci], accQ[3][ci]);
        __syncthreads();

        // accO += E @ V
        #pragma unroll 16
        for (int j = 0; j < 64; ++j) {
            float4 a4 = *(const float4*)&sET[j][rl];
            float4 b4 = *(const float4*)&sV[j][cl];
            const float a[4] = {a4.x, a4.y, a4.z, a4.w};
            const float b[4] = {b4.x, b4.y, b4.z, b4.w};
            #pragma unroll
            for (int ri = 0; ri < 4; ++ri)
                #pragma unroll
                for (int ci = 0; ci < 4; ++ci)
                    accO[ri][ci] += a[ri] * b[ci];
        }
    }

    __syncthreads();
    if (tid < 64) {
        const float inv = 1.0f / sS[tid];
        sInv[tid] = inv;
        g_SInv[rowbase + tid] = inv;
        g_C[(size_t)(rowbase + tid) * PSTR + 512] = sCs[tid];
    }
    __syncthreads();

    // first-term output (rel-val GEMM added by kernD)
    #pragma unroll
    for (int ri = 0; ri < 4; ++ri) {
        const float inv = sInv[rl + ri];
        float4 o = make_float4(accO[ri][0]*inv, accO[ri][1]*inv, accO[ri][2]*inv, accO[ri][3]*inv);
        *(float4*)(outp + (size_t)(rowbase + rl + ri) * 64 + cl) = o;
    }

    // pass2: normalize wbuf (pure streaming) + zero upper triangle
    for (int jb = 0; jb < 16; ++jb) {
        const int j0 = jb * 64;
        if (jb > ib) {
            const float4 z = make_float4(0.f, 0.f, 0.f, 0.f);
            for (int e = tid; e < 1024; e += 256) {
                int r = e >> 4, c4 = (e & 15) << 2;
                *(float4*)(wbuf + (size_t)(rowbase + r) * S_LEN + j0 + c4) = z;
            }
            continue;
        }
        for (int e = tid; e < 1024; e += 256) {
            int r = e >> 4, c4 = (e & 15) << 2;
            size_t addr = (size_t)(rowbase + r) * S_LEN + j0 + c4;
            float4 w = *(float4*)(wbuf + addr);
            const float f = sInv[r];
            w.x *= f; w.y *= f; w.z *= f; w.w *= f;
            *(float4*)(wbuf + addr) = w;
        }
    }

    if (i0 < 512) {  // zero-fill never-written g_C slots (m in (i,512))
        for (int idx = tid; idx < 64 * 512; idx += 256) {
            int r = idx >> 9, mm = idx & 511;
            if (mm > i0 + r) g_C[(size_t)(rowbase + r) * PSTR + mm] = 0.f;
        }
    }
}

// ---------------------------------------------------------------------------
// Kernel D: out += sInv[r] * (C_E @ Wv_rev), 256x64 tiles, 8x8 accum,
// K chunks of 64, truncated at m <= i0+255 (causal zeros above).
// ---------------------------------------------------------------------------
__global__ void __launch_bounds__(256) kernD(const float* __restrict__ Wv,
                                             float* __restrict__ outp) {
    extern __shared__ float dsmD[];
    float (*sCT)[260] = (float(*)[260])(dsmD);            // [m][r] 64x260
    float (*sB)[68]   = (float(*)[68])(dsmD + 16640);     // [m][d] 64x68
    const int r0 = blockIdx.x * 256;
    const int i0 = r0 & (S_LEN - 1);
    const int mEnd = min(NP, i0 + 256);
    const int tid = threadIdx.x;
    const int tx = tid & 7, ty = tid >> 3;   // tx: 8 col groups, ty: 32 row groups
    float acc[8][8] = {};

    for (int m0 = 0; m0 < mEnd; m0 += 64) {
        __syncthreads();
        #pragma unroll
        for (int l = 0; l < 16; ++l) {
            int e = tid + l * 256;
            int r = e & 255, c4 = (e >> 8) << 2;
            int mb = m0 + c4;
            float4 vv = make_float4(0.f,0.f,0.f,0.f);
            if (mb + 3 <= 512)
                vv = *(const float4*)(g_C + (size_t)(r0 + r)*PSTR + mb);
            else if (mb <= 512)
                vv.x = g_C[(size_t)(r0 + r)*PSTR + 512];
            sCT[c4+0][r]=vv.x; sCT[c4+1][r]=vv.y; sCT[c4+2][r]=vv.z; sCT[c4+3][r]=vv.w;
        }
        #pragma unroll
        for (int l = 0; l < 4; ++l) {
            int e = tid + l * 256;
            int mm = e >> 4, c4 = (e & 15) << 2;
            int m = m0 + mm;
            float4 vv = make_float4(0.f,0.f,0.f,0.f);
            if (m < NP) vv = *(const float4*)(Wv + (size_t)(512 - m)*64 + c4);
            *(float4*)&sB[mm][c4] = vv;
        }
        __syncthreads();
        #pragma unroll 8
        for (int m = 0; m < 64; ++m) {
            float a[8], b[8];
            *(float4*)&a[0] = *(const float4*)&sCT[m][4*ty];
            *(float4*)&a[4] = *(const float4*)&sCT[m][4*ty + 128];
            *(float4*)&b[0] = *(const float4*)&sB[m][4*tx];
            *(float4*)&b[4] = *(const float4*)&sB[m][4*tx + 32];
            #pragma unroll
            for (int ri = 0; ri < 8; ++ri)
                #pragma unroll
                for (int ci = 0; ci < 8; ++ci)
                    acc[ri][ci] += a[ri] * b[ci];
        }
    }
    #pragma unroll
    for (int rs = 0; rs < 8; ++rs) {
        const int r = r0 + ((rs < 4) ? 4*ty + rs : 128 + 4*ty + rs - 4);
        const float sinv = g_SInv[r];
        #pragma unroll
        for (int g = 0; g < 2; ++g) {
            size_t a = (size_t)r * 64 + 4*tx + g*32;
            float4 o = *(float4*)(outp + a);
            o.x += acc[rs][g*4+0]*sinv; o.y += acc[rs][g*4+1]*sinv;
            o.z += acc[rs][g*4+2]*sinv; o.w += acc[rs][g*4+3]*sinv;
            *(float4*)(outp + a) = o;
        }
    }
}

// ---------------------------------------------------------------------------
extern "C" void kernel_launch(void* const* d_in, const int* in_sizes, int n_in,
                              void* d_out, int out_size) {
    const float* q  = (const float*)d_in[0];
    const float* k  = (const float*)d_in[1];
    const float* v  = (const float*)d_in[2];
    const float* Wk = (const float*)d_in[3];
    const float* Wv = (const float*)d_in[4];

    float* outp = (float*)d_out;            // (B,H,S,D)
    float* wbuf = outp + OUT_ELEMS;         // (B,H,S,S) weights

    static bool attrs_set = false;
    if (!attrs_set) {
        cudaFuncSetAttribute(kernA,  cudaFuncAttributeMaxDynamicSharedMemorySize, 67584);
        cudaFuncSetAttribute(kernBC, cudaFuncAttributeMaxDynamicSharedMemorySize, 70400);
        cudaFuncSetAttribute(kernD,  cudaFuncAttributeMaxDynamicSharedMemorySize, 83968);
        attrs_set = true;
    }
    kernA<<<dim3(512, 5), 256, 67584>>>(q, Wk);
    kernBC<<<dim3(16, 64), 256, 70400>>>(q, k, v, wbuf, outp);
    kernD<<<dim3(256), 256, 83968>>>(Wv, outp);
}

// round 7
// speedup vs baseline: 1.0301x; 1.0301x over previous
#include <cuda_runtime.h>

#define S_LEN 1024
#define NP 513
#define PSTR 516
#define OUT_ELEMS 4194304
#define NROWS 65536

typedef unsigned long long ull;

__device__ float g_P[(size_t)NROWS * PSTR];   // P[row,p] = q[row]·Wk[p]
__device__ float g_C[(size_t)NROWS * PSTR];   // unnormalized shifted weights E
__device__ float g_SInv[NROWS];               // 1/sumexp per row

// packed fp32x2 FMA (sm_103a FFMA2 — only reachable via PTX)
__device__ __forceinline__ void ffma2(ull& d, ull a, ull b) {
    asm("fma.rn.f32x2 %0, %1, %2, %0;" : "+l"(d) : "l"(a), "l"(b));
}
__device__ __forceinline__ ull dup2(float x) {
    ull r;
    asm("mov.b64 %0, {%1, %1};" : "=l"(r) : "f"(x));
    return r;
}
__device__ __forceinline__ void unpk(float& lo, float& hi, ull v) {
    asm("mov.b64 {%0, %1}, %2;" : "=f"(lo), "=f"(hi) : "l"(v));
}

// ---------------------------------------------------------------------------
// Kernel A: P = Q @ Wk^T, 128x128 tiles, 8x8 accum (FFMA2), full-K resident
// ---------------------------------------------------------------------------
__global__ void __launch_bounds__(256) kernA(const float* __restrict__ q,
                                             const float* __restrict__ Wk) {
    const int r0 = blockIdx.x * 128;
    const int p0 = blockIdx.y * 128;
    const int i0 = r0 & (S_LEN - 1);
    if (p0 + 127 < 385 - i0) return;
    extern __shared__ float dsmA[];
    float (*sQT)[132] = (float(*)[132])(dsmA);          // [d][r]
    float (*sWT)[132] = (float(*)[132])(dsmA + 8448);   // [d][p-p0]
    const int tid = threadIdx.x;
    #pragma unroll
    for (int l = 0; l < 8; ++l) {
        int e = tid + l * 256;
        int r = e & 127, c4 = (e >> 7) << 2;
        float4 vv = *(const float4*)(q + (size_t)(r0 + r) * 64 + c4);
        sQT[c4+0][r]=vv.x; sQT[c4+1][r]=vv.y; sQT[c4+2][r]=vv.z; sQT[c4+3][r]=vv.w;
    }
    #pragma unroll
    for (int l = 0; l < 8; ++l) {
        int e = tid + l * 256;
        int r = e & 127, c4 = (e >> 7) << 2;
        int p = p0 + r;
        float4 vv = make_float4(0.f,0.f,0.f,0.f);
        if (p < NP) vv = *(const float4*)(Wk + (size_t)p * 64 + c4);
        sWT[c4+0][r]=vv.x; sWT[c4+1][r]=vv.y; sWT[c4+2][r]=vv.z; sWT[c4+3][r]=vv.w;
    }
    __syncthreads();
    const int tx = tid & 15, ty = tid >> 4;
    ull acc2[8][4] = {};
    #pragma unroll 4
    for (int d = 0; d < 64; ++d) {
        float4 a0 = *(const float4*)&sQT[d][4*ty];
        float4 a1 = *(const float4*)&sQT[d][4*ty + 64];
        ull b0 = *(const ull*)&sWT[d][4*tx];
        ull b1 = *(const ull*)&sWT[d][4*tx + 2];
        ull b2 = *(const ull*)&sWT[d][4*tx + 64];
        ull b3 = *(const ull*)&sWT[d][4*tx + 66];
        ull da[8] = {dup2(a0.x), dup2(a0.y), dup2(a0.z), dup2(a0.w),
                     dup2(a1.x), dup2(a1.y), dup2(a1.z), dup2(a1.w)};
        #pragma unroll
        for (int ri = 0; ri < 8; ++ri) {
            ffma2(acc2[ri][0], da[ri], b0);
            ffma2(acc2[ri][1], da[ri], b1);
            ffma2(acc2[ri][2], da[ri], b2);
            ffma2(acc2[ri][3], da[ri], b3);
        }
    }
    #pragma unroll
    for (int rs = 0; rs < 8; ++rs) {
        const int r = r0 + ((rs < 4) ? 4*ty + rs : 64 + 4*ty + rs - 4);
        const size_t row = (size_t)r * PSTR;
        float o[8];
        unpk(o[0], o[1], acc2[rs][0]); unpk(o[2], o[3], acc2[rs][1]);
        unpk(o[4], o[5], acc2[rs][2]); unpk(o[6], o[7], acc2[rs][3]);
        const int c0 = p0 + 4*tx;
        if (c0 <= 512)
            *(float4*)(g_P + row + c0) = make_float4(o[0],o[1],o[2],o[3]);
        const int c1 = p0 + 64 + 4*tx;
        if (c1 <= 512)
            *(float4*)(g_P + row + c1) = make_float4(o[4],o[5],o[6],o[7]);
    }
}

// ---------------------------------------------------------------------------
// Fused B+C: no-max softmax, FFMA2 inner loops (round-5 structure otherwise)
// ---------------------------------------------------------------------------
__global__ void __launch_bounds__(256) kernBC(const float* __restrict__ q,
                                              const float* __restrict__ kmat,
                                              const float* __restrict__ v,
                                              float* __restrict__ wbuf,
                                              float* __restrict__ outp) {
    extern __shared__ float dsm[];
    float (*sQT)[68] = (float(*)[68])(dsm);
    float (*sKT)[68] = (float(*)[68])(dsm + 4352);
    float (*sV)[68]  = (float(*)[68])(dsm + 8704);
    float (*sET)[68] = (float(*)[68])(dsm + 13056);
    float *sS   = dsm + 17408;
    float *sCs  = dsm + 17472;
    float *sInv = dsm + 17536;

    const int bh = blockIdx.y;
    const int ib = 15 - (int)blockIdx.x;     // heavy blocks first
    const int i0 = ib * 64;
    const int rowbase = bh * S_LEN + i0;
    const int tid = threadIdx.x;
    const int tx = tid & 15, ty = tid >> 4;
    const int rl = ty << 2, cl = tx << 2;

    for (int e = tid; e < 1024; e += 256) {
        int r = e >> 4, c4 = (e & 15) << 2;
        float4 vv = *(const float4*)(q + (size_t)(rowbase + r) * 64 + c4);
        sQT[c4+0][r]=vv.x; sQT[c4+1][r]=vv.y; sQT[c4+2][r]=vv.z; sQT[c4+3][r]=vv.w;
    }
    if (tid < 64) { sS[tid] = 0.f; sCs[tid] = 0.f; }

    ull accO2[4][2] = {};

    for (int jb = 0; jb <= ib; ++jb) {
        const int j0 = jb * 64;
        __syncthreads();
        for (int e = tid; e < 1024; e += 256) {
            int r = e >> 4, c4 = (e & 15) << 2;
            float4 vv = *(const float4*)(kmat + (size_t)(bh*S_LEN + j0 + r)*64 + c4);
            sKT[c4+0][r]=vv.x; sKT[c4+1][r]=vv.y; sKT[c4+2][r]=vv.z; sKT[c4+3][r]=vv.w;
        }
        #pragma unroll
        for (int l = 0; l < 4; ++l) {
            int e = tid + l * 256;
            int r = e >> 4, c4 = (e & 15) << 2;
            *(float4*)&sV[r][c4] = *(const float4*)(v + (size_t)(bh*S_LEN + j0 + r)*64 + c4);
        }
        __syncthreads();

        // QK^T (FFMA2): acc[ri][ci] += QT[d][ri]*KT[d][ci], packed along ci
        ull accQ2[4][2] = {};
        #pragma unroll 8
        for (int d = 0; d < 64; ++d) {
            float4 a4 = *(const float4*)&sQT[d][rl];
            ull b01 = *(const ull*)&sKT[d][cl];
            ull b23 = *(const ull*)&sKT[d][cl + 2];
            ull d0 = dup2(a4.x), d1 = dup2(a4.y), d2 = dup2(a4.z), d3 = dup2(a4.w);
            ffma2(accQ2[0][0], d0, b01); ffma2(accQ2[0][1], d0, b23);
            ffma2(accQ2[1][0], d1, b01); ffma2(accQ2[1][1], d1, b23);
            ffma2(accQ2[2][0], d2, b01); ffma2(accQ2[2][1], d2, b23);
            ffma2(accQ2[3][0], d3, b01); ffma2(accQ2[3][1], d3, b23);
        }
        float accQ[4][4];
        #pragma unroll
        for (int ri = 0; ri < 4; ++ri) {
            unpk(accQ[ri][0], accQ[ri][1], accQ2[ri][0]);
            unpk(accQ[ri][2], accQ[ri][3], accQ2[ri][1]);
        }

        // bias + mask + exp + rowsum + scatter
        #pragma unroll
        for (int ri = 0; ri < 4; ++ri) {
            const int r = rl + ri;
            const int i = i0 + r;
            const size_t prow = (size_t)(rowbase + r) * PSTR;
            #pragma unroll
            for (int ci = 0; ci < 4; ++ci) {
                const int j = j0 + cl + ci;
                int p = j - i + 512; if (p < 0) p = 0;
                float l = accQ[ri][ci] + g_P[prow + p];
                if (j > i) l = -1e30f;
                accQ[ri][ci] = __expf(l);
            }
            float se = accQ[ri][0] + accQ[ri][1] + accQ[ri][2] + accQ[ri][3];
            #pragma unroll
            for (int off = 8; off >= 1; off >>= 1)
                se += __shfl_xor_sync(0xffffffffu, se, off);
            if (tx == 0) sS[r] += se;
            #pragma unroll
            for (int ci = 0; ci < 4; ++ci) {
                const int mm = i - (j0 + cl + ci);
                if (mm >= 0) {
                    if (mm < 512) g_C[prow + mm] = accQ[ri][ci];
                    else          atomicAdd(&sCs[r], accQ[ri][ci]);
                }
            }
        }

        // E -> wbuf (raw) + transposed smem
        #pragma unroll
        for (int ri = 0; ri < 4; ++ri) {
            *(float4*)(wbuf + (size_t)(rowbase + rl + ri) * S_LEN + j0 + cl)
                = make_float4(accQ[ri][0], accQ[ri][1], accQ[ri][2], accQ[ri][3]);
            #pragma unroll
            for (int ci = 0; ci < 4; ++ci) sET[cl + ci][rl + ri] = accQ[ri][ci];
        }
        __syncthreads();

        // accO += E @ V (FFMA2): acc[ri][ci] += ET[j][ri]*V[j][ci], packed along ci
        #pragma unroll 8
        for (int j = 0; j < 64; ++j) {
            float4 a4 = *(const float4*)&sET[j][rl];
            ull b01 = *(const ull*)&sV[j][cl];
            ull b23 = *(const ull*)&sV[j][cl + 2];
            ull d0 = dup2(a4.x), d1 = dup2(a4.y), d2 = dup2(a4.z), d3 = dup2(a4.w);
            ffma2(accO2[0][0], d0, b01); ffma2(accO2[0][1], d0, b23);
            ffma2(accO2[1][0], d1, b01); ffma2(accO2[1][1], d1, b23);
            ffma2(accO2[2][0], d2, b01); ffma2(accO2[2][1], d2, b23);
            ffma2(accO2[3][0], d3, b01); ffma2(accO2[3][1], d3, b23);
        }
    }

    __syncthreads();
    if (tid < 64) {
        const float inv = 1.0f / sS[tid];
        sInv[tid] = inv;
        g_SInv[rowbase + tid] = inv;
        g_C[(size_t)(rowbase + tid) * PSTR + 512] = sCs[tid];
    }
    __syncthreads();

    // first-term output (rel-val GEMM added by kernD)
    #pragma unroll
    for (int ri = 0; ri < 4; ++ri) {
        float o[4];
        unpk(o[0], o[1], accO2[ri][0]);
        unpk(o[2], o[3], accO2[ri][1]);
        const float inv = sInv[rl + ri];
        *(float4*)(outp + (size_t)(rowbase + rl + ri) * 64 + cl)
            = make_float4(o[0]*inv, o[1]*inv, o[2]*inv, o[3]*inv);
    }

    // pass2: normalize wbuf (pure streaming) + zero upper triangle
    for (int jb = 0; jb < 16; ++jb) {
        const int j0 = jb * 64;
        if (jb > ib) {
            const float4 z = make_float4(0.f, 0.f, 0.f, 0.f);
            for (int e = tid; e < 1024; e += 256) {
                int r = e >> 4, c4 = (e & 15) << 2;
                *(float4*)(wbuf + (size_t)(rowbase + r) * S_LEN + j0 + c4) = z;
            }
            continue;
        }
        for (int e = tid; e < 1024; e += 256) {
            int r = e >> 4, c4 = (e & 15) << 2;
            size_t addr = (size_t)(rowbase + r) * S_LEN + j0 + c4;
            float4 w = *(float4*)(wbuf + addr);
            const float f = sInv[r];
            w.x *= f; w.y *= f; w.z *= f; w.w *= f;
            *(float4*)(wbuf + addr) = w;
        }
    }

    if (i0 < 512) {  // zero-fill never-written g_C slots (m in (i,512))
        for (int idx = tid; idx < 64 * 512; idx += 256) {
            int r = idx >> 9, mm = idx & 511;
            if (mm > i0 + r) g_C[(size_t)(rowbase + r) * PSTR + mm] = 0.f;
        }
    }
}

// ---------------------------------------------------------------------------
// Kernel D: out += sInv[r] * (C_E @ Wv_rev), 256x64 tiles, 8x8 accum (FFMA2)
// ---------------------------------------------------------------------------
__global__ void __launch_bounds__(256) kernD(const float* __restrict__ Wv,
                                             float* __restrict__ outp) {
    extern __shared__ float dsmD[];
    float (*sCT)[260] = (float(*)[260])(dsmD);            // [m][r] 64x260
    float (*sB)[68]   = (float(*)[68])(dsmD + 16640);     // [m][d] 64x68
    const int r0 = blockIdx.x * 256;
    const int i0 = r0 & (S_LEN - 1);
    const int mEnd = min(NP, i0 + 256);
    const int tid = threadIdx.x;
    const int tx = tid & 7, ty = tid >> 3;
    ull acc2[8][4] = {};

    for (int m0 = 0; m0 < mEnd; m0 += 64) {
        __syncthreads();
        #pragma unroll
        for (int l = 0; l < 16; ++l) {
            int e = tid + l * 256;
            int r = e & 255, c4 = (e >> 8) << 2;
            int mb = m0 + c4;
            float4 vv = make_float4(0.f,0.f,0.f,0.f);
            if (mb + 3 <= 512)
                vv = *(const float4*)(g_C + (size_t)(r0 + r)*PSTR + mb);
            else if (mb <= 512)
                vv.x = g_C[(size_t)(r0 + r)*PSTR + 512];
            sCT[c4+0][r]=vv.x; sCT[c4+1][r]=vv.y; sCT[c4+2][r]=vv.z; sCT[c4+3][r]=vv.w;
        }
        #pragma unroll
        for (int l = 0; l < 4; ++l) {
            int e = tid + l * 256;
            int mm = e >> 4, c4 = (e & 15) << 2;
            int m = m0 + mm;
            float4 vv = make_float4(0.f,0.f,0.f,0.f);
            if (m < NP) vv = *(const float4*)(Wv + (size_t)(512 - m)*64 + c4);
            *(float4*)&sB[mm][c4] = vv;
        }
        __syncthreads();
        #pragma unroll 4
        for (int m = 0; m < 64; ++m) {
            float4 a0 = *(const float4*)&sCT[m][4*ty];
            float4 a1 = *(const float4*)&sCT[m][4*ty + 128];
            ull b0 = *(const ull*)&sB[m][4*tx];
            ull b1 = *(const ull*)&sB[m][4*tx + 2];
            ull b2 = *(const ull*)&sB[m][4*tx + 32];
            ull b3 = *(const ull*)&sB[m][4*tx + 34];
            ull da[8] = {dup2(a0.x), dup2(a0.y), dup2(a0.z), dup2(a0.w),
                         dup2(a1.x), dup2(a1.y), dup2(a1.z), dup2(a1.w)};
            #pragma unroll
            for (int ri = 0; ri < 8; ++ri) {
                ffma2(acc2[ri][0], da[ri], b0);
                ffma2(acc2[ri][1], da[ri], b1);
                ffma2(acc2[ri][2], da[ri], b2);
                ffma2(acc2[ri][3], da[ri], b3);
            }
        }
    }
    #pragma unroll
    for (int rs = 0; rs < 8; ++rs) {
        const int r = r0 + ((rs < 4) ? 4*ty + rs : 128 + 4*ty + rs - 4);
        const float sinv = g_SInv[r];
        float oo[8];
        unpk(oo[0], oo[1], acc2[rs][0]); unpk(oo[2], oo[3], acc2[rs][1]);
        unpk(oo[4], oo[5], acc2[rs][2]); unpk(oo[6], oo[7], acc2[rs][3]);
        #pragma unroll
        for (int g = 0; g < 2; ++g) {
            size_t a = (size_t)r * 64 + 4*tx + g*32;
            float4 o = *(float4*)(outp + a);
            o.x += oo[g*4+0]*sinv; o.y += oo[g*4+1]*sinv;
            o.z += oo[g*4+2]*sinv; o.w += oo[g*4+3]*sinv;
            *(float4*)(outp + a) = o;
        }
    }
}

// ---------------------------------------------------------------------------
extern "C" void kernel_launch(void* const* d_in, const int* in_sizes, int n_in,
                              void* d_out, int out_size) {
    const float* q  = (const float*)d_in[0];
    const float* k  = (const float*)d_in[1];
    const float* v  = (const float*)d_in[2];
    const float* Wk = (const float*)d_in[3];
    const float* Wv = (const float*)d_in[4];

    float* outp = (float*)d_out;            // (B,H,S,D)
    float* wbuf = outp + OUT_ELEMS;         // (B,H,S,S) weights

    static bool attrs_set = false;
    if (!attrs_set) {
        cudaFuncSetAttribute(kernA,  cudaFuncAttributeMaxDynamicSharedMemorySize, 67584);
        cudaFuncSetAttribute(kernBC, cudaFuncAttributeMaxDynamicSharedMemorySize, 70400);
        cudaFuncSetAttribute(kernD,  cudaFuncAttributeMaxDynamicSharedMemorySize, 83968);
        attrs_set = true;
    }
    kernA<<<dim3(512, 5), 256, 67584>>>(q, Wk);
    kernBC<<<dim3(16, 64), 256, 70400>>>(q, k, v, wbuf, outp);
    kernD<<<dim3(256), 256, 83968>>>(Wv, outp);
}

// round 8
// speedup vs baseline: 1.0431x; 1.0126x over previous
#include <cuda_runtime.h>

#define S_LEN 1024
#define NP 513
#define PSTR 516
#define OUT_ELEMS 4194304
#define NROWS 65536

typedef unsigned long long ull;

__device__ float g_P[(size_t)NROWS * PSTR];   // P[row,p] = q[row]·Wk[p]
__device__ float g_C[(size_t)NROWS * PSTR];   // unnormalized shifted weights E
__device__ float g_SInv[NROWS];               // 1/sumexp per row

// packed fp32x2 FMA (sm_103a FFMA2 — only reachable via PTX)
__device__ __forceinline__ void ffma2(ull& d, ull a, ull b) {
    asm("fma.rn.f32x2 %0, %1, %2, %0;" : "+l"(d) : "l"(a), "l"(b));
}
__device__ __forceinline__ ull dup2(float x) {
    ull r;
    asm("mov.b64 %0, {%1, %1};" : "=l"(r) : "f"(x));
    return r;
}
__device__ __forceinline__ void unpk(float& lo, float& hi, ull v) {
    asm("mov.b64 {%0, %1}, %2;" : "=f"(lo), "=f"(hi) : "l"(v));
}
__device__ __forceinline__ void cp_async16(unsigned s, const void* g) {
    asm volatile("cp.async.ca.shared.global [%0], [%1], 16;" :: "r"(s), "l"(g));
}

// ---------------------------------------------------------------------------
// Kernel A: P = Q @ Wk^T, 128x128 tiles, 8x8 accum (FFMA2), full-K resident
// ---------------------------------------------------------------------------
__global__ void __launch_bounds__(256) kernA(const float* __restrict__ q,
                                             const float* __restrict__ Wk) {
    const int r0 = blockIdx.x * 128;
    const int p0 = blockIdx.y * 128;
    const int i0 = r0 & (S_LEN - 1);
    if (p0 + 127 < 385 - i0) return;
    extern __shared__ float dsmA[];
    float (*sQT)[132] = (float(*)[132])(dsmA);          // [d][r]
    float (*sWT)[132] = (float(*)[132])(dsmA + 8448);   // [d][p-p0]
    const int tid = threadIdx.x;
    #pragma unroll
    for (int l = 0; l < 8; ++l) {
        int e = tid + l * 256;
        int r = e & 127, c4 = (e >> 7) << 2;
        float4 vv = *(const float4*)(q + (size_t)(r0 + r) * 64 + c4);
        sQT[c4+0][r]=vv.x; sQT[c4+1][r]=vv.y; sQT[c4+2][r]=vv.z; sQT[c4+3][r]=vv.w;
    }
    #pragma unroll
    for (int l = 0; l < 8; ++l) {
        int e = tid + l * 256;
        int r = e & 127, c4 = (e >> 7) << 2;
        int p = p0 + r;
        float4 vv = make_float4(0.f,0.f,0.f,0.f);
        if (p < NP) vv = *(const float4*)(Wk + (size_t)p * 64 + c4);
        sWT[c4+0][r]=vv.x; sWT[c4+1][r]=vv.y; sWT[c4+2][r]=vv.z; sWT[c4+3][r]=vv.w;
    }
    __syncthreads();
    const int tx = tid & 15, ty = tid >> 4;
    ull acc2[8][4] = {};
    #pragma unroll 4
    for (int d = 0; d < 64; ++d) {
        float4 a0 = *(const float4*)&sQT[d][4*ty];
        float4 a1 = *(const float4*)&sQT[d][4*ty + 64];
        ull b0 = *(const ull*)&sWT[d][4*tx];
        ull b1 = *(const ull*)&sWT[d][4*tx + 2];
        ull b2 = *(const ull*)&sWT[d][4*tx + 64];
        ull b3 = *(const ull*)&sWT[d][4*tx + 66];
        ull da[8] = {dup2(a0.x), dup2(a0.y), dup2(a0.z), dup2(a0.w),
                     dup2(a1.x), dup2(a1.y), dup2(a1.z), dup2(a1.w)};
        #pragma unroll
        for (int ri = 0; ri < 8; ++ri) {
            ffma2(acc2[ri][0], da[ri], b0);
            ffma2(acc2[ri][1], da[ri], b1);
            ffma2(acc2[ri][2], da[ri], b2);
            ffma2(acc2[ri][3], da[ri], b3);
        }
    }
    #pragma unroll
    for (int rs = 0; rs < 8; ++rs) {
        const int r = r0 + ((rs < 4) ? 4*ty + rs : 64 + 4*ty + rs - 4);
        const size_t row = (size_t)r * PSTR;
        float o[8];
        unpk(o[0], o[1], acc2[rs][0]); unpk(o[2], o[3], acc2[rs][1]);
        unpk(o[4], o[5], acc2[rs][2]); unpk(o[6], o[7], acc2[rs][3]);
        const int c0 = p0 + 4*tx;
        if (c0 <= 512)
            *(float4*)(g_P + row + c0) = make_float4(o[0],o[1],o[2],o[3]);
        const int c1 = p0 + 64 + 4*tx;
        if (c1 <= 512)
            *(float4*)(g_P + row + c1) = make_float4(o[4],o[5],o[6],o[7]);
    }
}

// ---------------------------------------------------------------------------
// Fused B+C: no-max softmax, FFMA2, pipelined loads:
//   V via cp.async (hidden behind K-commit + QK GEMM)
//   K via register prefetch (hidden behind exp + E@V)
// ---------------------------------------------------------------------------
__global__ void __launch_bounds__(256) kernBC(const float* __restrict__ q,
                                              const float* __restrict__ kmat,
                                              const float* __restrict__ v,
                                              float* __restrict__ wbuf,
                                              float* __restrict__ outp) {
    extern __shared__ float dsm[];
    float (*sQT)[68] = (float(*)[68])(dsm);
    float (*sKT)[68] = (float(*)[68])(dsm + 4352);
    float (*sV)[68]  = (float(*)[68])(dsm + 8704);
    float (*sET)[68] = (float(*)[68])(dsm + 13056);
    float *sS   = dsm + 17408;
    float *sCs  = dsm + 17472;
    float *sInv = dsm + 17536;

    const int bh = blockIdx.y;
    const int ib = 15 - (int)blockIdx.x;     // heavy blocks first
    const int i0 = ib * 64;
    const int rowbase = bh * S_LEN + i0;
    const int tid = threadIdx.x;
    const int tx = tid & 15, ty = tid >> 4;
    const int rl = ty << 2, cl = tx << 2;

    const unsigned sV_u32 = (unsigned)__cvta_generic_to_shared(&sV[0][0]);
    const int pr = tid >> 4, pc4 = (tid & 15) << 2;   // loader mapping

    for (int e = tid; e < 1024; e += 256) {
        int r = e >> 4, c4 = (e & 15) << 2;
        float4 vv = *(const float4*)(q + (size_t)(rowbase + r) * 64 + c4);
        sQT[c4+0][r]=vv.x; sQT[c4+1][r]=vv.y; sQT[c4+2][r]=vv.z; sQT[c4+3][r]=vv.w;
    }
    if (tid < 64) { sS[tid] = 0.f; sCs[tid] = 0.f; }

    ull accO2[4][2] = {};

    // prefetch K tile 0 into registers
    float4 kr[4];
    {
        const float* ks = kmat + (size_t)(bh * S_LEN) * 64;
        #pragma unroll
        for (int l = 0; l < 4; ++l)
            kr[l] = *(const float4*)(ks + (size_t)(pr + l*16) * 64 + pc4);
    }

    for (int jb = 0; jb <= ib; ++jb) {
        const int j0 = jb * 64;
        __syncthreads();   // sKT/sV/sET free

        // async V load for this tile (consumed after 3rd barrier)
        {
            const float* vs = v + (size_t)(bh*S_LEN + j0) * 64;
            #pragma unroll
            for (int l = 0; l < 4; ++l) {
                int e = tid + l * 256;
                int r = e >> 4, c4 = (e & 15) << 2;
                cp_async16(sV_u32 + (unsigned)(r*68 + c4)*4u, vs + (size_t)r*64 + c4);
            }
            asm volatile("cp.async.commit_group;" ::: "memory");
        }

        // commit prefetched K tile (transposed)
        #pragma unroll
        for (int l = 0; l < 4; ++l) {
            int r = pr + l * 16;
            sKT[pc4+0][r]=kr[l].x; sKT[pc4+1][r]=kr[l].y;
            sKT[pc4+2][r]=kr[l].z; sKT[pc4+3][r]=kr[l].w;
        }
        __syncthreads();   // sKT ready (V not needed yet)

        // QK^T (FFMA2)
        ull accQ2[4][2] = {};
        #pragma unroll 8
        for (int d = 0; d < 64; ++d) {
            float4 a4 = *(const float4*)&sQT[d][rl];
            ull b01 = *(const ull*)&sKT[d][cl];
            ull b23 = *(const ull*)&sKT[d][cl + 2];
            ull d0 = dup2(a4.x), d1 = dup2(a4.y), d2 = dup2(a4.z), d3 = dup2(a4.w);
            ffma2(accQ2[0][0], d0, b01); ffma2(accQ2[0][1], d0, b23);
            ffma2(accQ2[1][0], d1, b01); ffma2(accQ2[1][1], d1, b23);
            ffma2(accQ2[2][0], d2, b01); ffma2(accQ2[2][1], d2, b23);
            ffma2(accQ2[3][0], d3, b01); ffma2(accQ2[3][1], d3, b23);
        }

        // issue K prefetch for next tile (hidden behind exp + E@V)
        if (jb < ib) {
            const float* ks = kmat + (size_t)(bh*S_LEN + j0 + 64) * 64;
            #pragma unroll
            for (int l = 0; l < 4; ++l)
                kr[l] = *(const float4*)(ks + (size_t)(pr + l*16) * 64 + pc4);
        }

        float accQ[4][4];
        #pragma unroll
        for (int ri = 0; ri < 4; ++ri) {
            unpk(accQ[ri][0], accQ[ri][1], accQ2[ri][0]);
            unpk(accQ[ri][2], accQ[ri][3], accQ2[ri][1]);
        }

        // bias + mask + exp + rowsum + scatter
        #pragma unroll
        for (int ri = 0; ri < 4; ++ri) {
            const int r = rl + ri;
            const int i = i0 + r;
            const size_t prow = (size_t)(rowbase + r) * PSTR;
            #pragma unroll
            for (int ci = 0; ci < 4; ++ci) {
                const int j = j0 + cl + ci;
                int p = j - i + 512; if (p < 0) p = 0;
                float l = accQ[ri][ci] + g_P[prow + p];
                if (j > i) l = -1e30f;
                accQ[ri][ci] = __expf(l);
            }
            float se = accQ[ri][0] + accQ[ri][1] + accQ[ri][2] + accQ[ri][3];
            #pragma unroll
            for (int off = 8; off >= 1; off >>= 1)
                se += __shfl_xor_sync(0xffffffffu, se, off);
            if (tx == 0) sS[r] += se;
            #pragma unroll
            for (int ci = 0; ci < 4; ++ci) {
                const int mm = i - (j0 + cl + ci);
                if (mm >= 0) {
                    if (mm < 512) g_C[prow + mm] = accQ[ri][ci];
                    else          atomicAdd(&sCs[r], accQ[ri][ci]);
                }
            }
        }

        // E -> wbuf (raw) + transposed smem
        #pragma unroll
        for (int ri = 0; ri < 4; ++ri) {
            *(float4*)(wbuf + (size_t)(rowbase + rl + ri) * S_LEN + j0 + cl)
                = make_float4(accQ[ri][0], accQ[ri][1], accQ[ri][2], accQ[ri][3]);
            #pragma unroll
            for (int ci = 0; ci < 4; ++ci) sET[cl + ci][rl + ri] = accQ[ri][ci];
        }
        asm volatile("cp.async.wait_group 0;" ::: "memory");
        __syncthreads();   // sET + sV ready

        // accO += E @ V (FFMA2)
        #pragma unroll 8
        for (int j = 0; j < 64; ++j) {
            float4 a4 = *(const float4*)&sET[j][rl];
            ull b01 = *(const ull*)&sV[j][cl];
            ull b23 = *(const ull*)&sV[j][cl + 2];
            ull d0 = dup2(a4.x), d1 = dup2(a4.y), d2 = dup2(a4.z), d3 = dup2(a4.w);
            ffma2(accO2[0][0], d0, b01); ffma2(accO2[0][1], d0, b23);
            ffma2(accO2[1][0], d1, b01); ffma2(accO2[1][1], d1, b23);
            ffma2(accO2[2][0], d2, b01); ffma2(accO2[2][1], d2, b23);
            ffma2(accO2[3][0], d3, b01); ffma2(accO2[3][1], d3, b23);
        }
    }

    __syncthreads();
    if (tid < 64) {
        const float inv = 1.0f / sS[tid];
        sInv[tid] = inv;
        g_SInv[rowbase + tid] = inv;
        g_C[(size_t)(rowbase + tid) * PSTR + 512] = sCs[tid];
    }
    __syncthreads();

    // first-term output (rel-val GEMM added by kernD)
    #pragma unroll
    for (int ri = 0; ri < 4; ++ri) {
        float o[4];
        unpk(o[0], o[1], accO2[ri][0]);
        unpk(o[2], o[3], accO2[ri][1]);
        const float inv = sInv[rl + ri];
        *(float4*)(outp + (size_t)(rowbase + rl + ri) * 64 + cl)
            = make_float4(o[0]*inv, o[1]*inv, o[2]*inv, o[3]*inv);
    }

    // pass2: normalize wbuf (pure streaming) + zero upper triangle
    for (int jb = 0; jb < 16; ++jb) {
        const int j0 = jb * 64;
        if (jb > ib) {
            const float4 z = make_float4(0.f, 0.f, 0.f, 0.f);
            for (int e = tid; e < 1024; e += 256) {
                int r = e >> 4, c4 = (e & 15) << 2;
                *(float4*)(wbuf + (size_t)(rowbase + r) * S_LEN + j0 + c4) = z;
            }
            continue;
        }
        for (int e = tid; e < 1024; e += 256) {
            int r = e >> 4, c4 = (e & 15) << 2;
            size_t addr = (size_t)(rowbase + r) * S_LEN + j0 + c4;
            float4 w = *(float4*)(wbuf + addr);
            const float f = sInv[r];
            w.x *= f; w.y *= f; w.z *= f; w.w *= f;
            *(float4*)(wbuf + addr) = w;
        }
    }

    if (i0 < 512) {  // zero-fill never-written g_C slots (m in (i,512))
        for (int idx = tid; idx < 64 * 512; idx += 256) {
            int r = idx >> 9, mm = idx & 511;
            if (mm > i0 + r) g_C[(size_t)(rowbase + r) * PSTR + mm] = 0.f;
        }
    }
}

// ---------------------------------------------------------------------------
// Kernel D: out += sInv[r] * (C_E @ Wv_rev), 256x64 tiles, 8x8 accum (FFMA2)
// ---------------------------------------------------------------------------
__global__ void __launch_bounds__(256) kernD(const float* __restrict__ Wv,
                                             float* __restrict__ outp) {
    extern __shared__ float dsmD[];
    float (*sCT)[260] = (float(*)[260])(dsmD);            // [m][r] 64x260
    float (*sB)[68]   = (float(*)[68])(dsmD + 16640);     // [m][d] 64x68
    const int r0 = blockIdx.x * 256;
    const int i0 = r0 & (S_LEN - 1);
    const int mEnd = min(NP, i0 + 256);
    const int tid = threadIdx.x;
    const int tx = tid & 7, ty = tid >> 3;
    ull acc2[8][4] = {};

    for (int m0 = 0; m0 < mEnd; m0 += 64) {
        __syncthreads();
        #pragma unroll
        for (int l = 0; l < 16; ++l) {
            int e = tid + l * 256;
            int r = e & 255, c4 = (e >> 8) << 2;
            int mb = m0 + c4;
            float4 vv = make_float4(0.f,0.f,0.f,0.f);
            if (mb + 3 <= 512)
                vv = *(const float4*)(g_C + (size_t)(r0 + r)*PSTR + mb);
            else if (mb <= 512)
                vv.x = g_C[(size_t)(r0 + r)*PSTR + 512];
            sCT[c4+0][r]=vv.x; sCT[c4+1][r]=vv.y; sCT[c4+2][r]=vv.z; sCT[c4+3][r]=vv.w;
        }
        #pragma unroll
        for (int l = 0; l < 4; ++l) {
            int e = tid + l * 256;
            int mm = e >> 4, c4 = (e & 15) << 2;
            int m = m0 + mm;
            float4 vv = make_float4(0.f,0.f,0.f,0.f);
            if (m < NP) vv = *(const float4*)(Wv + (size_t)(512 - m)*64 + c4);
            *(float4*)&sB[mm][c4] = vv;
        }
        __syncthreads();
        #pragma unroll 4
        for (int m = 0; m < 64; ++m) {
            float4 a0 = *(const float4*)&sCT[m][4*ty];
            float4 a1 = *(const float4*)&sCT[m][4*ty + 128];
            ull b0 = *(const ull*)&sB[m][4*tx];
            ull b1 = *(const ull*)&sB[m][4*tx + 2];
            ull b2 = *(const ull*)&sB[m][4*tx + 32];
            ull b3 = *(const ull*)&sB[m][4*tx + 34];
            ull da[8] = {dup2(a0.x), dup2(a0.y), dup2(a0.z), dup2(a0.w),
                         dup2(a1.x), dup2(a1.y), dup2(a1.z), dup2(a1.w)};
            #pragma unroll
            for (int ri = 0; ri < 8; ++ri) {
                ffma2(acc2[ri][0], da[ri], b0);
                ffma2(acc2[ri][1], da[ri], b1);
                ffma2(acc2[ri][2], da[ri], b2);
                ffma2(acc2[ri][3], da[ri], b3);
            }
        }
    }
    #pragma unroll
    for (int rs = 0; rs < 8; ++rs) {
        const int r = r0 + ((rs < 4) ? 4*ty + rs : 128 + 4*ty + rs - 4);
        const float sinv = g_SInv[r];
        float oo[8];
        unpk(oo[0], oo[1], acc2[rs][0]); unpk(oo[2], oo[3], acc2[rs][1]);
        unpk(oo[4], oo[5], acc2[rs][2]); unpk(oo[6], oo[7], acc2[rs][3]);
        #pragma unroll
        for (int g = 0; g < 2; ++g) {
            size_t a = (size_t)r * 64 + 4*tx + g*32;
            float4 o = *(float4*)(outp + a);
            o.x += oo[g*4+0]*sinv; o.y += oo[g*4+1]*sinv;
            o.z += oo[g*4+2]*sinv; o.w += oo[g*4+3]*sinv;
            *(float4*)(outp + a) = o;
        }
    }
}

// ---------------------------------------------------------------------------
extern "C" void kernel_launch(void* const* d_in, const int* in_sizes, int n_in,
                              void* d_out, int out_size) {
    const float* q  = (const float*)d_in[0];
    const float* k  = (const float*)d_in[1];
    const float* v  = (const float*)d_in[2];
    const float* Wk = (const float*)d_in[3];
    const float* Wv = (const float*)d_in[4];

    float* outp = (float*)d_out;            // (B,H,S,D)
    float* wbuf = outp + OUT_ELEMS;         // (B,H,S,S) weights

    static bool attrs_set = false;
    if (!attrs_set) {
        cudaFuncSetAttribute(kernA,  cudaFuncAttributeMaxDynamicSharedMemorySize, 67584);
        cudaFuncSetAttribute(kernBC, cudaFuncAttributeMaxDynamicSharedMemorySize, 70400);
        cudaFuncSetAttribute(kernD,  cudaFuncAttributeMaxDynamicSharedMemorySize, 83968);
        attrs_set = true;
    }
    kernA<<<dim3(512, 5), 256, 67584>>>(q, Wk);
    kernBC<<<dim3(16, 64), 256, 70400>>>(q, k, v, wbuf, outp);
    kernD<<<dim3(256), 256, 83968>>>(Wv, outp);
}

// round 9
// speedup vs baseline: 1.0492x; 1.0058x over previous
#include <cuda_runtime.h>

#define S_LEN 1024
#define NP 513
#define PSTR 516
#define OUT_ELEMS 4194304
#define NROWS 65536

typedef unsigned long long ull;

__device__ float g_P[(size_t)NROWS * PSTR];   // P[row,p] = q[row]·Wk[p]
__device__ float g_C[(size_t)NROWS * PSTR];   // unnormalized shifted weights E
__device__ float g_SInv[NROWS];               // 1/sumexp per row

// packed fp32x2 FMA (sm_103a FFMA2 — only reachable via PTX)
__device__ __forceinline__ void ffma2(ull& d, ull a, ull b) {
    asm("fma.rn.f32x2 %0, %1, %2, %0;" : "+l"(d) : "l"(a), "l"(b));
}
__device__ __forceinline__ ull dup2(float x) {
    ull r;
    asm("mov.b64 %0, {%1, %1};" : "=l"(r) : "f"(x));
    return r;
}
__device__ __forceinline__ void unpk(float& lo, float& hi, ull v) {
    asm("mov.b64 {%0, %1}, %2;" : "=f"(lo), "=f"(hi) : "l"(v));
}

// ---------------------------------------------------------------------------
// Kernel A: P = Q @ Wk^T, 128x128 tiles, 8x8 accum (FFMA2), full-K resident
// ---------------------------------------------------------------------------
__global__ void __launch_bounds__(256) kernA(const float* __restrict__ q,
                                             const float* __restrict__ Wk) {
    const int r0 = blockIdx.x * 128;
    const int p0 = blockIdx.y * 128;
    const int i0 = r0 & (S_LEN - 1);
    if (p0 + 127 < 385 - i0) return;
    extern __shared__ float dsmA[];
    float (*sQT)[132] = (float(*)[132])(dsmA);          // [d][r]
    float (*sWT)[132] = (float(*)[132])(dsmA + 8448);   // [d][p-p0]
    const int tid = threadIdx.x;
    #pragma unroll
    for (int l = 0; l < 8; ++l) {
        int e = tid + l * 256;
        int r = e & 127, c4 = (e >> 7) << 2;
        float4 vv = *(const float4*)(q + (size_t)(r0 + r) * 64 + c4);
        sQT[c4+0][r]=vv.x; sQT[c4+1][r]=vv.y; sQT[c4+2][r]=vv.z; sQT[c4+3][r]=vv.w;
    }
    #pragma unroll
    for (int l = 0; l < 8; ++l) {
        int e = tid + l * 256;
        int r = e & 127, c4 = (e >> 7) << 2;
        int p = p0 + r;
        float4 vv = make_float4(0.f,0.f,0.f,0.f);
        if (p < NP) vv = *(const float4*)(Wk + (size_t)p * 64 + c4);
        sWT[c4+0][r]=vv.x; sWT[c4+1][r]=vv.y; sWT[c4+2][r]=vv.z; sWT[c4+3][r]=vv.w;
    }
    __syncthreads();
    const int tx = tid & 15, ty = tid >> 4;
    ull acc2[8][4] = {};
    #pragma unroll 4
    for (int d = 0; d < 64; ++d) {
        float4 a0 = *(const float4*)&sQT[d][4*ty];
        float4 a1 = *(const float4*)&sQT[d][4*ty + 64];
        ull b0 = *(const ull*)&sWT[d][4*tx];
        ull b1 = *(const ull*)&sWT[d][4*tx + 2];
        ull b2 = *(const ull*)&sWT[d][4*tx + 64];
        ull b3 = *(const ull*)&sWT[d][4*tx + 66];
        ull da[8] = {dup2(a0.x), dup2(a0.y), dup2(a0.z), dup2(a0.w),
                     dup2(a1.x), dup2(a1.y), dup2(a1.z), dup2(a1.w)};
        #pragma unroll
        for (int ri = 0; ri < 8; ++ri) {
            ffma2(acc2[ri][0], da[ri], b0);
            ffma2(acc2[ri][1], da[ri], b1);
            ffma2(acc2[ri][2], da[ri], b2);
            ffma2(acc2[ri][3], da[ri], b3);
        }
    }
    #pragma unroll
    for (int rs = 0; rs < 8; ++rs) {
        const int r = r0 + ((rs < 4) ? 4*ty + rs : 64 + 4*ty + rs - 4);
        const size_t row = (size_t)r * PSTR;
        float o[8];
        unpk(o[0], o[1], acc2[rs][0]); unpk(o[2], o[3], acc2[rs][1]);
        unpk(o[4], o[5], acc2[rs][2]); unpk(o[6], o[7], acc2[rs][3]);
        const int c0 = p0 + 4*tx;
        if (c0 <= 512)
            *(float4*)(g_P + row + c0) = make_float4(o[0],o[1],o[2],o[3]);
        const int c1 = p0 + 64 + 4*tx;
        if (c1 <= 512)
            *(float4*)(g_P + row + c1) = make_float4(o[4],o[5],o[6],o[7]);
    }
}

// ---------------------------------------------------------------------------
// Fused B+C: no-max softmax, FFMA2, sET aliased onto sKT -> 53KB smem,
// 4 CTA/SM. 4 barriers per tile; work placed between them.
// ---------------------------------------------------------------------------
__global__ void __launch_bounds__(256, 4) kernBC(const float* __restrict__ q,
                                                 const float* __restrict__ kmat,
                                                 const float* __restrict__ v,
                                                 float* __restrict__ wbuf,
                                                 float* __restrict__ outp) {
    extern __shared__ float dsm[];
    float (*sQT)[68] = (float(*)[68])(dsm);          // [d][r]
    float (*sKE)[68] = (float(*)[68])(dsm + 4352);   // K^T [d][j], then E^T [j][r]
    float (*sV)[68]  = (float(*)[68])(dsm + 8704);   // [j][d]
    float *sS   = dsm + 13056;
    float *sCs  = dsm + 13120;
    float *sInv = dsm + 13184;

    const int bh = blockIdx.y;
    const int ib = 15 - (int)blockIdx.x;     // heavy blocks first
    const int i0 = ib * 64;
    const int rowbase = bh * S_LEN + i0;
    const int tid = threadIdx.x;
    const int tx = tid & 15, ty = tid >> 4;
    const int rl = ty << 2, cl = tx << 2;

    for (int e = tid; e < 1024; e += 256) {
        int r = e >> 4, c4 = (e & 15) << 2;
        float4 vv = *(const float4*)(q + (size_t)(rowbase + r) * 64 + c4);
        sQT[c4+0][r]=vv.x; sQT[c4+1][r]=vv.y; sQT[c4+2][r]=vv.z; sQT[c4+3][r]=vv.w;
    }
    if (tid < 64) { sS[tid] = 0.f; sCs[tid] = 0.f; }

    ull accO2[4][2] = {};

    for (int jb = 0; jb <= ib; ++jb) {
        const int j0 = jb * 64;
        __syncthreads();   // (1) prev E@V done: sKE, sV writable

        // load K (transposed) + V
        #pragma unroll
        for (int l = 0; l < 4; ++l) {
            int e = tid + l * 256;
            int r = e >> 4, c4 = (e & 15) << 2;
            float4 vv = *(const float4*)(kmat + (size_t)(bh*S_LEN + j0 + r)*64 + c4);
            sKE[c4+0][r]=vv.x; sKE[c4+1][r]=vv.y; sKE[c4+2][r]=vv.z; sKE[c4+3][r]=vv.w;
            *(float4*)&sV[r][c4] = *(const float4*)(v + (size_t)(bh*S_LEN + j0 + r)*64 + c4);
        }
        __syncthreads();   // (2) tiles ready

        // QK^T (FFMA2)
        ull accQ2[4][2] = {};
        #pragma unroll 8
        for (int d = 0; d < 64; ++d) {
            float4 a4 = *(const float4*)&sQT[d][rl];
            ull b01 = *(const ull*)&sKE[d][cl];
            ull b23 = *(const ull*)&sKE[d][cl + 2];
            ull d0 = dup2(a4.x), d1 = dup2(a4.y), d2 = dup2(a4.z), d3 = dup2(a4.w);
            ffma2(accQ2[0][0], d0, b01); ffma2(accQ2[0][1], d0, b23);
            ffma2(accQ2[1][0], d1, b01); ffma2(accQ2[1][1], d1, b23);
            ffma2(accQ2[2][0], d2, b01); ffma2(accQ2[2][1], d2, b23);
            ffma2(accQ2[3][0], d3, b01); ffma2(accQ2[3][1], d3, b23);
        }

        float accQ[4][4];
        #pragma unroll
        for (int ri = 0; ri < 4; ++ri) {
            unpk(accQ[ri][0], accQ[ri][1], accQ2[ri][0]);
            unpk(accQ[ri][2], accQ[ri][3], accQ2[ri][1]);
        }

        // bias + mask + exp + rowsum + scatter (no sKE access here)
        #pragma unroll
        for (int ri = 0; ri < 4; ++ri) {
            const int r = rl + ri;
            const int i = i0 + r;
            const size_t prow = (size_t)(rowbase + r) * PSTR;
            #pragma unroll
            for (int ci = 0; ci < 4; ++ci) {
                const int j = j0 + cl + ci;
                int p = j - i + 512; if (p < 0) p = 0;
                float l = accQ[ri][ci] + g_P[prow + p];
                if (j > i) l = -1e30f;
                accQ[ri][ci] = __expf(l);
            }
            float se = accQ[ri][0] + accQ[ri][1] + accQ[ri][2] + accQ[ri][3];
            #pragma unroll
            for (int off = 8; off >= 1; off >>= 1)
                se += __shfl_xor_sync(0xffffffffu, se, off);
            if (tx == 0) sS[r] += se;
            #pragma unroll
            for (int ci = 0; ci < 4; ++ci) {
                const int mm = i - (j0 + cl + ci);
                if (mm >= 0) {
                    if (mm < 512) g_C[prow + mm] = accQ[ri][ci];
                    else          atomicAdd(&sCs[r], accQ[ri][ci]);
                }
            }
        }
        // E -> wbuf (raw)
        #pragma unroll
        for (int ri = 0; ri < 4; ++ri)
            *(float4*)(wbuf + (size_t)(rowbase + rl + ri) * S_LEN + j0 + cl)
                = make_float4(accQ[ri][0], accQ[ri][1], accQ[ri][2], accQ[ri][3]);

        __syncthreads();   // (3) all QK reads of sKE done -> write E^T over it
        #pragma unroll
        for (int ri = 0; ri < 4; ++ri)
            #pragma unroll
            for (int ci = 0; ci < 4; ++ci) sKE[cl + ci][rl + ri] = accQ[ri][ci];
        __syncthreads();   // (4) E^T ready

        // accO += E @ V (FFMA2)
        #pragma unroll 8
        for (int j = 0; j < 64; ++j) {
            float4 a4 = *(const float4*)&sKE[j][rl];
            ull b01 = *(const ull*)&sV[j][cl];
            ull b23 = *(const ull*)&sV[j][cl + 2];
            ull d0 = dup2(a4.x), d1 = dup2(a4.y), d2 = dup2(a4.z), d3 = dup2(a4.w);
            ffma2(accO2[0][0], d0, b01); ffma2(accO2[0][1], d0, b23);
            ffma2(accO2[1][0], d1, b01); ffma2(accO2[1][1], d1, b23);
            ffma2(accO2[2][0], d2, b01); ffma2(accO2[2][1], d2, b23);
            ffma2(accO2[3][0], d3, b01); ffma2(accO2[3][1], d3, b23);
        }
    }

    __syncthreads();
    if (tid < 64) {
        const float inv = 1.0f / sS[tid];
        sInv[tid] = inv;
        g_SInv[rowbase + tid] = inv;
        g_C[(size_t)(rowbase + tid) * PSTR + 512] = sCs[tid];
    }
    __syncthreads();

    // first-term output (rel-val GEMM added by kernD)
    #pragma unroll
    for (int ri = 0; ri < 4; ++ri) {
        float o[4];
        unpk(o[0], o[1], accO2[ri][0]);
        unpk(o[2], o[3], accO2[ri][1]);
        const float inv = sInv[rl + ri];
        *(float4*)(outp + (size_t)(rowbase + rl + ri) * 64 + cl)
            = make_float4(o[0]*inv, o[1]*inv, o[2]*inv, o[3]*inv);
    }

    // pass2: normalize wbuf (pure streaming) + zero upper triangle
    for (int jb = 0; jb < 16; ++jb) {
        const int j0 = jb * 64;
        if (jb > ib) {
            const float4 z = make_float4(0.f, 0.f, 0.f, 0.f);
            for (int e = tid; e < 1024; e += 256) {
                int r = e >> 4, c4 = (e & 15) << 2;
                *(float4*)(wbuf + (size_t)(rowbase + r) * S_LEN + j0 + c4) = z;
            }
            continue;
        }
        for (int e = tid; e < 1024; e += 256) {
            int r = e >> 4, c4 = (e & 15) << 2;
            size_t addr = (size_t)(rowbase + r) * S_LEN + j0 + c4;
            float4 w = *(float4*)(wbuf + addr);
            const float f = sInv[r];
            w.x *= f; w.y *= f; w.z *= f; w.w *= f;
            *(float4*)(wbuf + addr) = w;
        }
    }

    if (i0 < 512) {  // zero-fill never-written g_C slots (m in (i,512))
        for (int idx = tid; idx < 64 * 512; idx += 256) {
            int r = idx >> 9, mm = idx & 511;
            if (mm > i0 + r) g_C[(size_t)(rowbase + r) * PSTR + mm] = 0.f;
        }
    }
}

// ---------------------------------------------------------------------------
// Kernel D: out += sInv[r] * (C_E @ Wv_rev), 256x64 tiles, 8x8 accum (FFMA2)
// ---------------------------------------------------------------------------
__global__ void __launch_bounds__(256) kernD(const float* __restrict__ Wv,
                                             float* __restrict__ outp) {
    extern __shared__ float dsmD[];
    float (*sCT)[260] = (float(*)[260])(dsmD);            // [m][r] 64x260
    float (*sB)[68]   = (float(*)[68])(dsmD + 16640);     // [m][d] 64x68
    const int r0 = blockIdx.x * 256;
    const int i0 = r0 & (S_LEN - 1);
    const int mEnd = min(NP, i0 + 256);
    const int tid = threadIdx.x;
    const int tx = tid & 7, ty = tid >> 3;
    ull acc2[8][4] = {};

    for (int m0 = 0; m0 < mEnd; m0 += 64) {
        __syncthreads();
        #pragma unroll
        for (int l = 0; l < 16; ++l) {
            int e = tid + l * 256;
            int r = e & 255, c4 = (e >> 8) << 2;
            int mb = m0 + c4;
            float4 vv = make_float4(0.f,0.f,0.f,0.f);
            if (mb + 3 <= 512)
                vv = *(const float4*)(g_C + (size_t)(r0 + r)*PSTR + mb);
            else if (mb <= 512)
                vv.x = g_C[(size_t)(r0 + r)*PSTR + 512];
            sCT[c4+0][r]=vv.x; sCT[c4+1][r]=vv.y; sCT[c4+2][r]=vv.z; sCT[c4+3][r]=vv.w;
        }
        #pragma unroll
        for (int l = 0; l < 4; ++l) {
            int e = tid + l * 256;
            int mm = e >> 4, c4 = (e & 15) << 2;
            int m = m0 + mm;
            float4 vv = make_float4(0.f,0.f,0.f,0.f);
            if (m < NP) vv = *(const float4*)(Wv + (size_t)(512 - m)*64 + c4);
            *(float4*)&sB[mm][c4] = vv;
        }
        __syncthreads();
        #pragma unroll 4
        for (int m = 0; m < 64; ++m) {
            float4 a0 = *(const float4*)&sCT[m][4*ty];
            float4 a1 = *(const float4*)&sCT[m][4*ty + 128];
            ull b0 = *(const ull*)&sB[m][4*tx];
            ull b1 = *(const ull*)&sB[m][4*tx + 2];
            ull b2 = *(const ull*)&sB[m][4*tx + 32];
            ull b3 = *(const ull*)&sB[m][4*tx + 34];
            ull da[8] = {dup2(a0.x), dup2(a0.y), dup2(a0.z), dup2(a0.w),
                         dup2(a1.x), dup2(a1.y), dup2(a1.z), dup2(a1.w)};
            #pragma unroll
            for (int ri = 0; ri < 8; ++ri) {
                ffma2(acc2[ri][0], da[ri], b0);
                ffma2(acc2[ri][1], da[ri], b1);
                ffma2(acc2[ri][2], da[ri], b2);
                ffma2(acc2[ri][3], da[ri], b3);
            }
        }
    }
    #pragma unroll
    for (int rs = 0; rs < 8; ++rs) {
        const int r = r0 + ((rs < 4) ? 4*ty + rs : 128 + 4*ty + rs - 4);
        const float sinv = g_SInv[r];
        float oo[8];
        unpk(oo[0], oo[1], acc2[rs][0]); unpk(oo[2], oo[3], acc2[rs][1]);
        unpk(oo[4], oo[5], acc2[rs][2]); unpk(oo[6], oo[7], acc2[rs][3]);
        #pragma unroll
        for (int g = 0; g < 2; ++g) {
            size_t a = (size_t)r * 64 + 4*tx + g*32;
            float4 o = *(float4*)(outp + a);
            o.x += oo[g*4+0]*sinv; o.y += oo[g*4+1]*sinv;
            o.z += oo[g*4+2]*sinv; o.w += oo[g*4+3]*sinv;
            *(float4*)(outp + a) = o;
        }
    }
}

// ---------------------------------------------------------------------------
extern "C" void kernel_launch(void* const* d_in, const int* in_sizes, int n_in,
                              void* d_out, int out_size) {
    const float* q  = (const float*)d_in[0];
    const float* k  = (const float*)d_in[1];
    const float* v  = (const float*)d_in[2];
    const float* Wk = (const float*)d_in[3];
    const float* Wv = (const float*)d_in[4];

    float* outp = (float*)d_out;            // (B,H,S,D)
    float* wbuf = outp + OUT_ELEMS;         // (B,H,S,S) weights

    static bool attrs_set = false;
    if (!attrs_set) {
        cudaFuncSetAttribute(kernA,  cudaFuncAttributeMaxDynamicSharedMemorySize, 67584);
        cudaFuncSetAttribute(kernBC, cudaFuncAttributeMaxDynamicSharedMemorySize, 53248);
        cudaFuncSetAttribute(kernD,  cudaFuncAttributeMaxDynamicSharedMemorySize, 83968);
        attrs_set = true;
    }
    kernA<<<dim3(512, 5), 256, 67584>>>(q, Wk);
    kernBC<<<dim3(16, 64), 256, 53248>>>(q, k, v, wbuf, outp);
    kernD<<<dim3(256), 256, 83968>>>(Wv, outp);
}

// round 10
// speedup vs baseline: 1.0821x; 1.0314x over previous
#include <cuda_runtime.h>

#define S_LEN 1024
#define NP 513
#define PSTR 516
#define OUT_ELEMS 4194304
#define NROWS 65536

typedef unsigned long long ull;

__device__ float g_P[(size_t)NROWS * PSTR];   // P[row,p] = q[row]·Wk[p]
__device__ float g_C[(size_t)NROWS * PSTR];   // unnormalized shifted weights E

// packed fp32x2 FMA (sm_103a FFMA2 — only reachable via PTX)
__device__ __forceinline__ void ffma2(ull& d, ull a, ull b) {
    asm("fma.rn.f32x2 %0, %1, %2, %0;" : "+l"(d) : "l"(a), "l"(b));
}
__device__ __forceinline__ ull dup2(float x) {
    ull r;
    asm("mov.b64 %0, {%1, %1};" : "=l"(r) : "f"(x));
    return r;
}
__device__ __forceinline__ void unpk(float& lo, float& hi, ull v) {
    asm("mov.b64 {%0, %1}, %2;" : "=f"(lo), "=f"(hi) : "l"(v));
}

// ---------------------------------------------------------------------------
// Kernel A: P = Q @ Wk^T, 128x128 tiles, 8x8 accum (FFMA2), full-K resident
// ---------------------------------------------------------------------------
__global__ void __launch_bounds__(256) kernA(const float* __restrict__ q,
                                             const float* __restrict__ Wk) {
    const int r0 = blockIdx.x * 128;
    const int p0 = blockIdx.y * 128;
    const int i0 = r0 & (S_LEN - 1);
    if (p0 + 127 < 385 - i0) return;
    extern __shared__ float dsmA[];
    float (*sQT)[132] = (float(*)[132])(dsmA);          // [d][r]
    float (*sWT)[132] = (float(*)[132])(dsmA + 8448);   // [d][p-p0]
    const int tid = threadIdx.x;
    #pragma unroll
    for (int l = 0; l < 8; ++l) {
        int e = tid + l * 256;
        int r = e & 127, c4 = (e >> 7) << 2;
        float4 vv = *(const float4*)(q + (size_t)(r0 + r) * 64 + c4);
        sQT[c4+0][r]=vv.x; sQT[c4+1][r]=vv.y; sQT[c4+2][r]=vv.z; sQT[c4+3][r]=vv.w;
    }
    #pragma unroll
    for (int l = 0; l < 8; ++l) {
        int e = tid + l * 256;
        int r = e & 127, c4 = (e >> 7) << 2;
        int p = p0 + r;
        float4 vv = make_float4(0.f,0.f,0.f,0.f);
        if (p < NP) vv = *(const float4*)(Wk + (size_t)p * 64 + c4);
        sWT[c4+0][r]=vv.x; sWT[c4+1][r]=vv.y; sWT[c4+2][r]=vv.z; sWT[c4+3][r]=vv.w;
    }
    __syncthreads();
    const int tx = tid & 15, ty = tid >> 4;
    ull acc2[8][4] = {};
    #pragma unroll 4
    for (int d = 0; d < 64; ++d) {
        float4 a0 = *(const float4*)&sQT[d][4*ty];
        float4 a1 = *(const float4*)&sQT[d][4*ty + 64];
        ull b0 = *(const ull*)&sWT[d][4*tx];
        ull b1 = *(const ull*)&sWT[d][4*tx + 2];
        ull b2 = *(const ull*)&sWT[d][4*tx + 64];
        ull b3 = *(const ull*)&sWT[d][4*tx + 66];
        ull da[8] = {dup2(a0.x), dup2(a0.y), dup2(a0.z), dup2(a0.w),
                     dup2(a1.x), dup2(a1.y), dup2(a1.z), dup2(a1.w)};
        #pragma unroll
        for (int ri = 0; ri < 8; ++ri) {
            ffma2(acc2[ri][0], da[ri], b0);
            ffma2(acc2[ri][1], da[ri], b1);
            ffma2(acc2[ri][2], da[ri], b2);
            ffma2(acc2[ri][3], da[ri], b3);
        }
    }
    #pragma unroll
    for (int rs = 0; rs < 8; ++rs) {
        const int r = r0 + ((rs < 4) ? 4*ty + rs : 64 + 4*ty + rs - 4);
        const size_t row = (size_t)r * PSTR;
        float o[8];
        unpk(o[0], o[1], acc2[rs][0]); unpk(o[2], o[3], acc2[rs][1]);
        unpk(o[4], o[5], acc2[rs][2]); unpk(o[6], o[7], acc2[rs][3]);
        const int c0 = p0 + 4*tx;
        if (c0 <= 512)
            *(float4*)(g_P + row + c0) = make_float4(o[0],o[1],o[2],o[3]);
        const int c1 = p0 + 64 + 4*tx;
        if (c1 <= 512)
            *(float4*)(g_P + row + c1) = make_float4(o[4],o[5],o[6],o[7]);
    }
}

// ---------------------------------------------------------------------------
// Fused B+C+D: pass1 flash loop -> sInv -> in-CTA rel-val GEMM (L2-hot g_C)
// -> output write -> pass2 wbuf fill from g_C.
// ---------------------------------------------------------------------------
__global__ void __launch_bounds__(256) kernBCD(const float* __restrict__ q,
                                               const float* __restrict__ kmat,
                                               const float* __restrict__ v,
                                               const float* __restrict__ Wv,
                                               float* __restrict__ wbuf,
                                               float* __restrict__ outp) {
    extern __shared__ float dsm[];
    float (*sQT)[68] = (float(*)[68])(dsm);          // [d][r]
    float (*sKE)[68] = (float(*)[68])(dsm + 4352);   // K^T, then E^T, then C-chunk [m][r]
    float (*sV)[68]  = (float(*)[68])(dsm + 8704);   // V [j][d], then Wv_rev chunk [m][d]
    float *sS   = dsm + 13056;
    float *sCs  = dsm + 13120;
    float *sInv = dsm + 13184;

    const int bh = blockIdx.y;
    const int ib = 15 - (int)blockIdx.x;     // heavy blocks first
    const int i0 = ib * 64;
    const int rowbase = bh * S_LEN + i0;
    const int tid = threadIdx.x;
    const int tx = tid & 15, ty = tid >> 4;
    const int rl = ty << 2, cl = tx << 2;

    for (int e = tid; e < 1024; e += 256) {
        int r = e >> 4, c4 = (e & 15) << 2;
        float4 vv = *(const float4*)(q + (size_t)(rowbase + r) * 64 + c4);
        sQT[c4+0][r]=vv.x; sQT[c4+1][r]=vv.y; sQT[c4+2][r]=vv.z; sQT[c4+3][r]=vv.w;
    }
    if (tid < 64) { sS[tid] = 0.f; sCs[tid] = 0.f; }

    ull accO2[4][2] = {};

    // ---------------- pass1: flash loop ----------------
    for (int jb = 0; jb <= ib; ++jb) {
        const int j0 = jb * 64;
        __syncthreads();   // (1) prev E@V done: sKE, sV writable

        #pragma unroll
        for (int l = 0; l < 4; ++l) {
            int e = tid + l * 256;
            int r = e >> 4, c4 = (e & 15) << 2;
            float4 vv = *(const float4*)(kmat + (size_t)(bh*S_LEN + j0 + r)*64 + c4);
            sKE[c4+0][r]=vv.x; sKE[c4+1][r]=vv.y; sKE[c4+2][r]=vv.z; sKE[c4+3][r]=vv.w;
            *(float4*)&sV[r][c4] = *(const float4*)(v + (size_t)(bh*S_LEN + j0 + r)*64 + c4);
        }
        __syncthreads();   // (2) tiles ready

        // QK^T (FFMA2)
        ull accQ2[4][2] = {};
        #pragma unroll 8
        for (int d = 0; d < 64; ++d) {
            float4 a4 = *(const float4*)&sQT[d][rl];
            ull b01 = *(const ull*)&sKE[d][cl];
            ull b23 = *(const ull*)&sKE[d][cl + 2];
            ull d0 = dup2(a4.x), d1 = dup2(a4.y), d2 = dup2(a4.z), d3 = dup2(a4.w);
            ffma2(accQ2[0][0], d0, b01); ffma2(accQ2[0][1], d0, b23);
            ffma2(accQ2[1][0], d1, b01); ffma2(accQ2[1][1], d1, b23);
            ffma2(accQ2[2][0], d2, b01); ffma2(accQ2[2][1], d2, b23);
            ffma2(accQ2[3][0], d3, b01); ffma2(accQ2[3][1], d3, b23);
        }

        float accQ[4][4];
        #pragma unroll
        for (int ri = 0; ri < 4; ++ri) {
            unpk(accQ[ri][0], accQ[ri][1], accQ2[ri][0]);
            unpk(accQ[ri][2], accQ[ri][3], accQ2[ri][1]);
        }

        // bias + mask + exp + rowsum + scatter
        #pragma unroll
        for (int ri = 0; ri < 4; ++ri) {
            const int r = rl + ri;
            const int i = i0 + r;
            const size_t prow = (size_t)(rowbase + r) * PSTR;
            #pragma unroll
            for (int ci = 0; ci < 4; ++ci) {
                const int j = j0 + cl + ci;
                int p = j - i + 512; if (p < 0) p = 0;
                float l = accQ[ri][ci] + g_P[prow + p];
                if (j > i) l = -1e30f;
                accQ[ri][ci] = __expf(l);
            }
            float se = accQ[ri][0] + accQ[ri][1] + accQ[ri][2] + accQ[ri][3];
            #pragma unroll
            for (int off = 8; off >= 1; off >>= 1)
                se += __shfl_xor_sync(0xffffffffu, se, off);
            if (tx == 0) sS[r] += se;
            #pragma unroll
            for (int ci = 0; ci < 4; ++ci) {
                const int mm = i - (j0 + cl + ci);
                if (mm >= 0) {
                    if (mm < 512) {
                        g_C[prow + mm] = accQ[ri][ci];
                    } else {
                        atomicAdd(&sCs[r], accQ[ri][ci]);
                        // individual E unrecoverable from lumped slot -> raw to wbuf
                        wbuf[(size_t)(rowbase + r) * S_LEN + j0 + cl + ci] = accQ[ri][ci];
                    }
                }
            }
        }

        __syncthreads();   // (3) QK reads of sKE done -> overwrite with E^T
        #pragma unroll
        for (int ri = 0; ri < 4; ++ri)
            #pragma unroll
            for (int ci = 0; ci < 4; ++ci) sKE[cl + ci][rl + ri] = accQ[ri][ci];
        __syncthreads();   // (4) E^T ready

        // accO += E @ V (FFMA2)
        #pragma unroll 8
        for (int j = 0; j < 64; ++j) {
            float4 a4 = *(const float4*)&sKE[j][rl];
            ull b01 = *(const ull*)&sV[j][cl];
            ull b23 = *(const ull*)&sV[j][cl + 2];
            ull d0 = dup2(a4.x), d1 = dup2(a4.y), d2 = dup2(a4.z), d3 = dup2(a4.w);
            ffma2(accO2[0][0], d0, b01); ffma2(accO2[0][1], d0, b23);
            ffma2(accO2[1][0], d1, b01); ffma2(accO2[1][1], d1, b23);
            ffma2(accO2[2][0], d2, b01); ffma2(accO2[2][1], d2, b23);
            ffma2(accO2[3][0], d3, b01); ffma2(accO2[3][1], d3, b23);
        }
    }

    __syncthreads();
    if (tid < 64) {
        sInv[tid] = 1.0f / sS[tid];
        g_C[(size_t)(rowbase + tid) * PSTR + 512] = sCs[tid];
    }
    __syncthreads();

    // ---------------- D-phase: accO += C_E @ Wv_rev (L2-hot g_C) ----------------
    const int mEnd = min(NP, i0 + 64);
    for (int m0 = 0; m0 < mEnd; m0 += 64) {
        __syncthreads();   // chunk buffers free
        #pragma unroll
        for (int l = 0; l < 4; ++l) {
            int e = tid + l * 256;
            int r = e >> 4, c4 = (e & 15) << 2;
            const int mb = m0 + c4;
            const int irow = i0 + r;
            float4 vv = make_float4(0.f,0.f,0.f,0.f);
            if (mb <= 512)
                vv = *(const float4*)(g_C + (size_t)(rowbase + r)*PSTR + mb);
            float comp[4] = {vv.x, vv.y, vv.z, vv.w};
            #pragma unroll
            for (int t = 0; t < 4; ++t) {
                const int m = mb + t;
                const bool ok = (m < 512) ? (m <= irow) : (m == 512);
                sKE[c4 + t][r] = ok ? comp[t] : 0.f;
            }
        }
        #pragma unroll
        for (int l = 0; l < 4; ++l) {
            int e = tid + l * 256;
            int mm = e >> 4, c4 = (e & 15) << 2;
            const int m = m0 + mm;
            float4 vv = make_float4(0.f,0.f,0.f,0.f);
            if (m <= 512) vv = *(const float4*)(Wv + (size_t)(512 - m)*64 + c4);
            *(float4*)&sV[mm][c4] = vv;
        }
        __syncthreads();
        #pragma unroll 8
        for (int m = 0; m < 64; ++m) {
            float4 a4 = *(const float4*)&sKE[m][rl];
            ull b01 = *(const ull*)&sV[m][cl];
            ull b23 = *(const ull*)&sV[m][cl + 2];
            ull d0 = dup2(a4.x), d1 = dup2(a4.y), d2 = dup2(a4.z), d3 = dup2(a4.w);
            ffma2(accO2[0][0], d0, b01); ffma2(accO2[0][1], d0, b23);
            ffma2(accO2[1][0], d1, b01); ffma2(accO2[1][1], d1, b23);
            ffma2(accO2[2][0], d2, b01); ffma2(accO2[2][1], d2, b23);
            ffma2(accO2[3][0], d3, b01); ffma2(accO2[3][1], d3, b23);
        }
    }

    // final output: (E@V + C@Wv_rev) * sInv
    #pragma unroll
    for (int ri = 0; ri < 4; ++ri) {
        float o[4];
        unpk(o[0], o[1], accO2[ri][0]);
        unpk(o[2], o[3], accO2[ri][1]);
        const float inv = sInv[rl + ri];
        *(float4*)(outp + (size_t)(rowbase + rl + ri) * 64 + cl)
            = make_float4(o[0]*inv, o[1]*inv, o[2]*inv, o[3]*inv);
    }

    // ---------------- pass2: weights from g_C (L2-hot) ----------------
    for (int jb = 0; jb < 16; ++jb) {
        const int j0 = jb * 64;
        if (jb > ib) {
            const float4 z = make_float4(0.f, 0.f, 0.f, 0.f);
            for (int e = tid; e < 1024; e += 256) {
                int r = e >> 4, c4 = (e & 15) << 2;
                *(float4*)(wbuf + (size_t)(rowbase + r) * S_LEN + j0 + c4) = z;
            }
            continue;
        }
        for (int e = tid; e < 1024; e += 256) {
            int r = e >> 4, c4 = (e & 15) << 2;
            const int i = i0 + r;
            const size_t row = (size_t)(rowbase + r);
            const size_t addr = row * S_LEN + j0 + c4;
            const size_t prow = row * PSTR;
            const float f = sInv[r];
            float w[4];
            #pragma unroll
            for (int t = 0; t < 4; ++t) {
                const int j = j0 + c4 + t;
                const int mm = i - j;
                float eV = 0.f;
                if (mm >= 0) {
                    if (mm < 512) eV = g_C[prow + mm];
                    else          eV = wbuf[addr + t];   // raw E written in pass1
                }
                w[t] = eV * f;
            }
            *(float4*)(wbuf + addr) = make_float4(w[0], w[1], w[2], w[3]);
        }
    }
}

// ---------------------------------------------------------------------------
extern "C" void kernel_launch(void* const* d_in, const int* in_sizes, int n_in,
                              void* d_out, int out_size) {
    const float* q  = (const float*)d_in[0];
    const float* k  = (const float*)d_in[1];
    const float* v  = (const float*)d_in[2];
    const float* Wk = (const float*)d_in[3];
    const float* Wv = (const float*)d_in[4];

    float* outp = (float*)d_out;            // (B,H,S,D)
    float* wbuf = outp + OUT_ELEMS;         // (B,H,S,S) weights

    static bool attrs_set = false;
    if (!attrs_set) {
        cudaFuncSetAttribute(kernA,   cudaFuncAttributeMaxDynamicSharedMemorySize, 67584);
        cudaFuncSetAttribute(kernBCD, cudaFuncAttributeMaxDynamicSharedMemorySize, 53248);
        attrs_set = true;
    }
    kernA<<<dim3(512, 5), 256, 67584>>>(q, Wk);
    kernBCD<<<dim3(16, 64), 256, 53248>>>(q, k, v, Wv, wbuf, outp);
}